// round 13
// baseline (speedup 1.0000x reference)
#include <cuda_runtime.h>
#include <cuda_fp16.h>
#include <mma.h>
#include <math.h>

using namespace nvcuda;

#define B_  8
#define N_  1024
#define D_  256
#define H_  8
#define DH_ 32
#define R_  4
#define FF_ 1024
#define M_  (B_*N_)   // 8192 rows

// ---- scratch (device globals) ----
__device__ __half g_Qh[M_*D_];
__device__ __half g_Kh[M_*D_];
__device__ __half g_Vh[(size_t)M_*R_*D_];     // [n][r*256 + h*32 + d]
__device__ unsigned char g_adjB[(size_t)M_*N_];
__device__ __half g_Oh[M_*D_];
__device__ float g_T1[M_*D_];
__device__ float g_X[M_*D_];
__device__ __half g_Xh[M_*D_];
__device__ __half g_F1h[(size_t)M_*FF_];
__device__ float g_T2[M_*D_];

__device__ __forceinline__ float gelu_f(float x){
    return 0.5f*x*(1.0f + erff(x*0.70710678118654752440f));
}
__device__ __forceinline__ uint2 f4_to_h4(float4 v){
    __half2 lo = __floats2half2_rn(v.x, v.y);
    __half2 hi = __floats2half2_rn(v.z, v.w);
    uint2 r; r.x = *(unsigned*)&lo; r.y = *(unsigned*)&hi; return r;
}

// ---------------- PTX helpers ----------------
__device__ __forceinline__ unsigned sm32(const void* p){
    return (unsigned)__cvta_generic_to_shared(p);
}
__device__ __forceinline__ void cp16(unsigned dst, const void* src){
    asm volatile("cp.async.cg.shared.global [%0], [%1], 16;" :: "r"(dst), "l"(src) : "memory");
}
__device__ __forceinline__ void ldsm4(unsigned* r, unsigned a){
    asm volatile("ldmatrix.sync.aligned.m8n8.x4.shared.b16 {%0,%1,%2,%3}, [%4];"
        : "=r"(r[0]),"=r"(r[1]),"=r"(r[2]),"=r"(r[3]) : "r"(a));
}
__device__ __forceinline__ void ldsm4t(unsigned* r, unsigned a){
    asm volatile("ldmatrix.sync.aligned.m8n8.x4.trans.shared.b16 {%0,%1,%2,%3}, [%4];"
        : "=r"(r[0]),"=r"(r[1]),"=r"(r[2]),"=r"(r[3]) : "r"(a));
}
__device__ __forceinline__ void mma16816(float* c, const unsigned* a, unsigned b0, unsigned b1){
    asm volatile("mma.sync.aligned.m16n8k16.row.col.f32.f16.f16.f32 "
        "{%0,%1,%2,%3}, {%4,%5,%6,%7}, {%8,%9}, {%0,%1,%2,%3};"
        : "+f"(c[0]),"+f"(c[1]),"+f"(c[2]),"+f"(c[3])
        : "r"(a[0]),"r"(a[1]),"r"(a[2]),"r"(a[3]), "r"(b0),"r"(b1));
}

// =================== shared GEMM mainloop pieces ===================
// BM=128, BN=64, BK=32, 256 threads (8 warps 4x2), warp tile 32x32, fp32 accum.
// Two A-paths: float (converted) and half (direct).

template<bool GELU, bool HOUT>
__device__ __forceinline__ void gemm_epilogue(
    float* Cs, const float* bias, void* Cout, int ldc, float osc,
    int row0, int col0, int t)
{
    const int row = t >> 1, c0 = (t & 1)*32;
    #pragma unroll
    for (int i=0;i<8;i++){
        float4 v = *(const float4*)&Cs[row*72 + c0 + i*4];
        const int cg = col0 + c0 + i*4;
        v.x += bias[cg+0]; v.y += bias[cg+1]; v.z += bias[cg+2]; v.w += bias[cg+3];
        if (HOUT){ v.x*=osc; v.y*=osc; v.z*=osc; v.w*=osc; }
        if (GELU){ v.x=gelu_f(v.x); v.y=gelu_f(v.y); v.z=gelu_f(v.z); v.w=gelu_f(v.w); }
        if (HOUT){
            __half* Ch = (__half*)Cout;
            uint2 hv = f4_to_h4(v);
            *(uint2*)&Ch[(size_t)(row0+row)*ldc + cg] = hv;
        } else {
            float* Cf = (float*)Cout;
            *(float4*)&Cf[(size_t)(row0+row)*ldc + cg] = v;
        }
    }
}

__device__ __forceinline__ void gemm_mma_step(
    const __half* As, const __half* Bs, int wr, int wc,
    wmma::fragment<wmma::accumulator,16,16,16,float> acc[2][2])
{
    #pragma unroll
    for (int kk=0; kk<2; kk++){
        const int k16 = kk*16;
        wmma::fragment<wmma::matrix_a,16,16,16,__half,wmma::row_major> fa[2];
        wmma::fragment<wmma::matrix_b,16,16,16,__half,wmma::row_major> fb[2];
        #pragma unroll
        for (int i=0;i<2;i++)
            wmma::load_matrix_sync(fa[i], &As[(wr*32 + i*16)*40 + k16], 40);
        #pragma unroll
        for (int j=0;j<2;j++)
            wmma::load_matrix_sync(fb[j], &Bs[k16*72 + wc*32 + j*16], 72);
        #pragma unroll
        for (int i=0;i<2;i++)
            #pragma unroll
            for (int j=0;j<2;j++) wmma::mma_sync(acc[i][j], fa[i], fb[j], acc[i][j]);
    }
}

// ---- float-A version ----
template<bool GELU, bool HOUT>
__device__ __forceinline__ void gemm_body_f(
    const float* __restrict__ A, const float* __restrict__ Bm,
    const float* __restrict__ bias, void* __restrict__ Cout,
    int Ncols, int K, int ldc, float osc, int bx, int by)
{
    __shared__ float sm[9216];
    __half* As = (__half*)sm;                  // [128][40]
    __half* Bs = (__half*)sm + 5120;           // [32][72]
    float*  Cs = sm;                           // [128][72]

    const int t = threadIdx.x;
    const int w = t >> 5;
    const int wr = w >> 1, wc = w & 1;
    const int row0 = by*128, col0 = bx*64;

    const int rowA = t >> 1, cA = (t & 1)*16;
    const int rowB = t >> 3, cB = (t & 7)*8;

    wmma::fragment<wmma::accumulator,16,16,16,float> acc[2][2];
    #pragma unroll
    for (int i=0;i<2;i++)
        #pragma unroll
        for (int j=0;j<2;j++) wmma::fill_fragment(acc[i][j], 0.f);

    float4 pa[4], pb[2];
    {
        const float* ap = &A[(size_t)(row0+rowA)*K + cA];
        #pragma unroll
        for (int i=0;i<4;i++) pa[i] = *(const float4*)(ap + 4*i);
        const float* bp = &Bm[(size_t)rowB*Ncols + col0 + cB];
        #pragma unroll
        for (int i=0;i<2;i++) pb[i] = *(const float4*)(bp + 4*i);
    }

    for (int k0 = 0; k0 < K; k0 += 32){
        __syncthreads();
        {
            uint4 h0, h1;
            uint2 a0=f4_to_h4(pa[0]), a1=f4_to_h4(pa[1]), a2=f4_to_h4(pa[2]), a3=f4_to_h4(pa[3]);
            h0.x=a0.x; h0.y=a0.y; h0.z=a1.x; h0.w=a1.y;
            h1.x=a2.x; h1.y=a2.y; h1.z=a3.x; h1.w=a3.y;
            *(uint4*)&As[rowA*40 + cA]     = h0;
            *(uint4*)&As[rowA*40 + cA + 8] = h1;
            uint2 b0=f4_to_h4(pb[0]), b1=f4_to_h4(pb[1]);
            uint4 hb; hb.x=b0.x; hb.y=b0.y; hb.z=b1.x; hb.w=b1.y;
            *(uint4*)&Bs[rowB*72 + cB] = hb;
        }
        __syncthreads();

        if (k0 + 32 < K){
            const float* ap = &A[(size_t)(row0+rowA)*K + k0 + 32 + cA];
            #pragma unroll
            for (int i=0;i<4;i++) pa[i] = *(const float4*)(ap + 4*i);
            const float* bp = &Bm[(size_t)(k0+32+rowB)*Ncols + col0 + cB];
            #pragma unroll
            for (int i=0;i<2;i++) pb[i] = *(const float4*)(bp + 4*i);
        }
        gemm_mma_step(As, Bs, wr, wc, acc);
    }

    __syncthreads();
    #pragma unroll
    for (int i=0;i<2;i++)
        #pragma unroll
        for (int j=0;j<2;j++)
            wmma::store_matrix_sync(&Cs[(wr*32+i*16)*72 + wc*32 + j*16], acc[i][j], 72, wmma::mem_row_major);
    __syncthreads();
    gemm_epilogue<GELU,HOUT>(Cs, bias, Cout, ldc, osc, row0, col0, t);
}

// ---- half-A version ----
template<bool GELU, bool HOUT>
__device__ __forceinline__ void gemm_body_h(
    const __half* __restrict__ A, const float* __restrict__ Bm,
    const float* __restrict__ bias, void* __restrict__ Cout,
    int Ncols, int K, int ldc, int bx, int by)
{
    __shared__ float sm[9216];
    __half* As = (__half*)sm;                  // [128][40]
    __half* Bs = (__half*)sm + 5120;           // [32][72]
    float*  Cs = sm;                           // [128][72]

    const int t = threadIdx.x;
    const int w = t >> 5;
    const int wr = w >> 1, wc = w & 1;
    const int row0 = by*128, col0 = bx*64;

    const int rowA = t >> 1, cA = (t & 1)*16;
    const int rowB = t >> 3, cB = (t & 7)*8;

    wmma::fragment<wmma::accumulator,16,16,16,float> acc[2][2];
    #pragma unroll
    for (int i=0;i<2;i++)
        #pragma unroll
        for (int j=0;j<2;j++) wmma::fill_fragment(acc[i][j], 0.f);

    uint4 pa[2];
    float4 pb[2];
    {
        const __half* ap = &A[(size_t)(row0+rowA)*K + cA];
        pa[0] = *(const uint4*)ap;
        pa[1] = *(const uint4*)(ap + 8);
        const float* bp = &Bm[(size_t)rowB*Ncols + col0 + cB];
        #pragma unroll
        for (int i=0;i<2;i++) pb[i] = *(const float4*)(bp + 4*i);
    }

    for (int k0 = 0; k0 < K; k0 += 32){
        __syncthreads();
        {
            *(uint4*)&As[rowA*40 + cA]     = pa[0];
            *(uint4*)&As[rowA*40 + cA + 8] = pa[1];
            uint2 b0=f4_to_h4(pb[0]), b1=f4_to_h4(pb[1]);
            uint4 hb; hb.x=b0.x; hb.y=b0.y; hb.z=b1.x; hb.w=b1.y;
            *(uint4*)&Bs[rowB*72 + cB] = hb;
        }
        __syncthreads();

        if (k0 + 32 < K){
            const __half* ap = &A[(size_t)(row0+rowA)*K + k0 + 32 + cA];
            pa[0] = *(const uint4*)ap;
            pa[1] = *(const uint4*)(ap + 8);
            const float* bp = &Bm[(size_t)(k0+32+rowB)*Ncols + col0 + cB];
            #pragma unroll
            for (int i=0;i<2;i++) pb[i] = *(const float4*)(bp + 4*i);
        }
        gemm_mma_step(As, Bs, wr, wc, acc);
    }

    __syncthreads();
    #pragma unroll
    for (int i=0;i<2;i++)
        #pragma unroll
        for (int j=0;j<2;j++)
            wmma::store_matrix_sync(&Cs[(wr*32+i*16)*72 + wc*32 + j*16], acc[i][j], 72, wmma::mem_row_major);
    __syncthreads();
    gemm_epilogue<GELU,HOUT>(Cs, bias, Cout, ldc, 1.f, row0, col0, t);
}

struct QKVParams {
    const float* W[6];
    const float* bias[6];
    __half*      C[6];
    int          ldc[6];
    float        scale[6];
};

__global__ void __launch_bounds__(256) gemm_qkv(
    const float* __restrict__ A, QKVParams p)
{
    const int z = blockIdx.z;
    gemm_body_f<false,true>(A, p.W[z], p.bias[z], p.C[z], D_, D_, p.ldc[z],
                            p.scale[z], blockIdx.x, blockIdx.y);
}

// half-A, float-out (Wo, W2)
__global__ void __launch_bounds__(256) gemm_h_f(
    const __half* __restrict__ A, const float* __restrict__ Bm,
    const float* __restrict__ bias, float* __restrict__ C,
    int Ncols, int K, int ldc)
{
    gemm_body_h<false,false>(A, Bm, bias, C, Ncols, K, ldc, blockIdx.x, blockIdx.y);
}

// half-A, GELU, half-out (W1)
__global__ void __launch_bounds__(256) gemm_h_gelu_h(
    const __half* __restrict__ A, const float* __restrict__ Bm,
    const float* __restrict__ bias, __half* __restrict__ C,
    int Ncols, int K, int ldc)
{
    gemm_body_h<true,true>(A, Bm, bias, C, Ncols, K, ldc, blockIdx.x, blockIdx.y);
}

// adj int32 -> uint8
__global__ void __launch_bounds__(256) adj2byte(
    const int* __restrict__ adj, unsigned char* __restrict__ out)
{
    const size_t i = (size_t)blockIdx.x*256 + threadIdx.x;
    int4 v = ((const int4*)adj)[i];
    uchar4 o;
    o.x=(unsigned char)v.x; o.y=(unsigned char)v.y;
    o.z=(unsigned char)v.z; o.w=(unsigned char)v.w;
    ((uchar4*)out)[i] = o;
}

// =================== fast residual + LayerNorm (warp per row) ===================
// out = LN(X + Y) * g + beta; optionally also write half(out) to outh.
template<bool HCOPY>
__global__ void __launch_bounds__(256) ln_fast(
    const float* __restrict__ X, const float* __restrict__ Y,
    const float* __restrict__ g, const float* __restrict__ beta,
    float* __restrict__ out, __half* __restrict__ outh)
{
    const int w = threadIdx.x >> 5, l = threadIdx.x & 31;
    const size_t row = (size_t)blockIdx.x*8 + w;
    const int col = l*8;
    const float* xp = X + row*D_ + col;
    const float* yp = Y + row*D_ + col;
    float4 x0 = *(const float4*)xp, x1 = *(const float4*)(xp+4);
    float4 y0 = *(const float4*)yp, y1 = *(const float4*)(yp+4);
    float v[8];
    v[0]=x0.x+y0.x; v[1]=x0.y+y0.y; v[2]=x0.z+y0.z; v[3]=x0.w+y0.w;
    v[4]=x1.x+y1.x; v[5]=x1.y+y1.y; v[6]=x1.z+y1.z; v[7]=x1.w+y1.w;

    float s = v[0]+v[1]+v[2]+v[3]+v[4]+v[5]+v[6]+v[7];
    #pragma unroll
    for (int off=16; off>0; off>>=1) s += __shfl_xor_sync(0xffffffffu, s, off);
    const float mean = s * (1.0f/D_);
    float s2 = 0.f;
    #pragma unroll
    for (int i=0;i<8;i++){ const float d = v[i]-mean; s2 += d*d; }
    #pragma unroll
    for (int off=16; off>0; off>>=1) s2 += __shfl_xor_sync(0xffffffffu, s2, off);
    const float rstd = rsqrtf(s2*(1.0f/D_) + 1e-5f);

    float4 g0 = *(const float4*)&g[col],    g1v = *(const float4*)&g[col+4];
    float4 b0 = *(const float4*)&beta[col], b1v = *(const float4*)&beta[col+4];
    float4 o0, o1;
    o0.x=(v[0]-mean)*rstd*g0.x + b0.x;  o0.y=(v[1]-mean)*rstd*g0.y + b0.y;
    o0.z=(v[2]-mean)*rstd*g0.z + b0.z;  o0.w=(v[3]-mean)*rstd*g0.w + b0.w;
    o1.x=(v[4]-mean)*rstd*g1v.x + b1v.x; o1.y=(v[5]-mean)*rstd*g1v.y + b1v.y;
    o1.z=(v[6]-mean)*rstd*g1v.z + b1v.z; o1.w=(v[7]-mean)*rstd*g1v.w + b1v.w;
    float* op = out + row*D_ + col;
    *(float4*)op = o0; *(float4*)(op+4) = o1;
    if (HCOPY){
        uint2 h0 = f4_to_h4(o0), h1 = f4_to_h4(o1);
        uint4 hv; hv.x=h0.x; hv.y=h0.y; hv.z=h1.x; hv.w=h1.y;
        *(uint4*)&outh[row*D_ + col] = hv;
    }
}

// =================== relational flash attention: raw mma + cp.async ===================
#define BUFB 29696
#define ATTN_SMEM 60928

__device__ __forceinline__ void issue_tile(
    unsigned char* bufp, int t, int b, int h, int i0, int j0,
    const __half* __restrict__ Kg, const __half* __restrict__ Vg,
    const unsigned char* __restrict__ adjB)
{
    const int row = t>>2, seg = t&3;
    cp16(sm32(bufp + row*80 + seg*16),
         Kg + (size_t)(b*N_ + j0 + row)*D_ + h*DH_ + seg*8);
    cp16(sm32(bufp + 25600 + row*64 + seg*16),
         adjB + (size_t)(b*N_ + i0 + row)*N_ + j0 + seg*16);
    #pragma unroll
    for (int k2=0;k2<4;k2++){
        const int c = t + 256*k2;
        const int rj = c>>2, sg = c&3;
        const int r = rj>>6, j = rj&63;
        cp16(sm32(bufp + 5120 + rj*80 + sg*16),
             Vg + (size_t)(b*N_ + j0 + j)*(R_*D_) + r*D_ + h*DH_ + sg*8);
    }
}

__global__ void __launch_bounds__(256, 2) attn_mma(
    const __half* __restrict__ Qg, const __half* __restrict__ Kg,
    const __half* __restrict__ Vg, const unsigned char* __restrict__ adjB,
    __half* __restrict__ O)
{
    extern __shared__ unsigned char smn[];
    unsigned char* buf0 = smn;
    unsigned char* buf1 = smn + BUFB;
    float* pmax = (float*)(smn + 2*BUFB);          // [2][64]
    float* psum = (float*)(smn + 2*BUFB + 512);    // [2][64]
    float* mrow = (float*)(smn + 2*BUFB + 1024);   // [64]
    float* lrow = (float*)(smn + 2*BUFB + 1280);   // [64]

    const int t = threadIdx.x, l = t & 31, w = t >> 5;
    const int rg = w >> 1, jh = w & 1;
    const int it = blockIdx.x, h = blockIdx.y, b = blockIdx.z;
    const int i0 = it*64;
    const int r0row = l >> 2, cp2 = (l & 3)*2;
    const int rowg0 = rg*16 + r0row;
    const int grp = l >> 3, li = l & 7;

    // stage Q tile into buf1 head
    {
        const int row = t>>2, seg = t&3;
        uint4 qv = *(const uint4*)(Qg + (size_t)(b*N_ + i0 + row)*D_ + h*DH_ + seg*8);
        *(uint4*)(buf1 + row*80 + seg*16) = qv;
    }
    if (t < 64){ mrow[t] = -1e30f; lrow[t] = 0.f; }
    issue_tile(buf0, t, b, h, i0, 0, Kg, Vg, adjB);
    asm volatile("cp.async.commit_group;" ::: "memory");
    __syncthreads();

    // Q fragments (A-operand: m1=row+8, m2=k+8)
    unsigned qf[2][4];
    {
        const int qrow = rg*16 + li + (grp&1)*8;
        #pragma unroll
        for (int kb=0;kb<2;kb++){
            unsigned a = sm32(buf1 + qrow*80 + (kb*16 + ((grp>>1)&1)*8)*2);
            ldsm4(qf[kb], a);
        }
    }

    float Od[4][4];
    #pragma unroll
    for (int i=0;i<4;i++){ Od[i][0]=0;Od[i][1]=0;Od[i][2]=0;Od[i][3]=0; }

    for (int jt = 0; jt < 16; jt++){
        unsigned char* bufc = (jt & 1) ? buf1 : buf0;
        unsigned char* bufn = (jt & 1) ? buf0 : buf1;
        __syncthreads();
        if (jt + 1 < 16){
            issue_tile(bufn, t, b, h, i0, (jt+1)*64, Kg, Vg, adjB);
            asm volatile("cp.async.commit_group;" ::: "memory");
            asm volatile("cp.async.wait_group 1;" ::: "memory");
        } else {
            asm volatile("cp.async.wait_group 0;" ::: "memory");
        }
        __syncthreads();

        // K fragments (B-operand)
        unsigned kf[2][2][4];
        {
            const int krow = jh*32 + li + ((grp>>1)&1)*8;
            #pragma unroll
            for (int kb=0;kb<2;kb++)
                #pragma unroll
                for (int p=0;p<2;p++){
                    unsigned a = sm32(bufc + (krow + p*16)*80 + (kb*16 + (grp&1)*8)*2);
                    ldsm4(kf[kb][p], a);
                }
        }

        // scores
        float sd[4][4];
        #pragma unroll
        for (int t8=0;t8<4;t8++){
            sd[t8][0]=0;sd[t8][1]=0;sd[t8][2]=0;sd[t8][3]=0;
            #pragma unroll
            for (int kb=0;kb<2;kb++){
                const int p = t8>>1, q = (t8&1)*2;
                mma16816(sd[t8], qf[kb], kf[kb][p][q], kf[kb][p][q+1]);
            }
        }

        // online softmax
        float mx0 = -1e30f, mx1 = -1e30f;
        #pragma unroll
        for (int t8=0;t8<4;t8++){
            mx0 = fmaxf(mx0, fmaxf(sd[t8][0], sd[t8][1]));
            mx1 = fmaxf(mx1, fmaxf(sd[t8][2], sd[t8][3]));
        }
        mx0 = fmaxf(mx0, __shfl_xor_sync(0xffffffffu, mx0, 1));
        mx0 = fmaxf(mx0, __shfl_xor_sync(0xffffffffu, mx0, 2));
        mx1 = fmaxf(mx1, __shfl_xor_sync(0xffffffffu, mx1, 1));
        mx1 = fmaxf(mx1, __shfl_xor_sync(0xffffffffu, mx1, 2));
        if ((l&3)==0){
            pmax[jh*64 + rowg0]     = mx0;
            pmax[jh*64 + rowg0 + 8] = mx1;
        }
        __syncthreads();
        const float mold0 = mrow[rowg0], mold1 = mrow[rowg0+8];
        const float mn0 = fmaxf(mold0, fmaxf(pmax[rowg0],   pmax[64+rowg0]));
        const float mn1 = fmaxf(mold1, fmaxf(pmax[rowg0+8], pmax[64+rowg0+8]));
        const float c0 = __expf(mold0 - mn0), c1 = __expf(mold1 - mn1);
        float s0 = 0.f, s1 = 0.f;
        #pragma unroll
        for (int t8=0;t8<4;t8++){
            sd[t8][0] = __expf(sd[t8][0] - mn0);
            sd[t8][1] = __expf(sd[t8][1] - mn0);
            sd[t8][2] = __expf(sd[t8][2] - mn1);
            sd[t8][3] = __expf(sd[t8][3] - mn1);
            s0 += sd[t8][0] + sd[t8][1];
            s1 += sd[t8][2] + sd[t8][3];
        }
        s0 += __shfl_xor_sync(0xffffffffu, s0, 1);
        s0 += __shfl_xor_sync(0xffffffffu, s0, 2);
        s1 += __shfl_xor_sync(0xffffffffu, s1, 1);
        s1 += __shfl_xor_sync(0xffffffffu, s1, 2);
        if ((l&3)==0){
            psum[jh*64 + rowg0]     = s0;
            psum[jh*64 + rowg0 + 8] = s1;
        }
        __syncthreads();
        if (jh==0 && (l&3)==0){
            lrow[rowg0]   = lrow[rowg0]  *c0 + psum[rowg0]   + psum[64+rowg0];
            lrow[rowg0+8] = lrow[rowg0+8]*c1 + psum[rowg0+8] + psum[64+rowg0+8];
            mrow[rowg0]   = mn0;
            mrow[rowg0+8] = mn1;
        }

        #pragma unroll
        for (int t8=0;t8<4;t8++){
            Od[t8][0]*=c0; Od[t8][1]*=c0; Od[t8][2]*=c1; Od[t8][3]*=c1;
        }

        // p -> half2 + adj codes
        unsigned h2r[4][2], ax2[4][2];
        const unsigned char* adjT = bufc + 25600;
        #pragma unroll
        for (int t8=0;t8<4;t8++){
            __half2 p01 = __floats2half2_rn(sd[t8][0], sd[t8][1]);
            __half2 p23 = __floats2half2_rn(sd[t8][2], sd[t8][3]);
            h2r[t8][0] = *(unsigned*)&p01;
            h2r[t8][1] = *(unsigned*)&p23;
            const int colo = jh*32 + t8*8 + cp2;
            unsigned a0 = *(const unsigned short*)(adjT + rowg0*64 + colo);
            unsigned a1 = *(const unsigned short*)(adjT + (rowg0+8)*64 + colo);
            ax2[t8][0] = (a0 & 0xffu) | ((a0 & 0xff00u) << 8);
            ax2[t8][1] = (a1 & 0xffu) | ((a1 & 0xff00u) << 8);
        }

        // PV: Od += sum_r (P .* (adj==r)) @ V_r
        const unsigned char* Vb = bufc + 5120;
        #pragma unroll
        for (int r=0;r<R_;r++){
            const unsigned rr2 = (unsigned)r * 0x00010001u;
            #pragma unroll
            for (int s=0;s<2;s++){
                unsigned am[4];
                am[0] = h2r[2*s  ][0] & __vcmpeq2(ax2[2*s  ][0], rr2);
                am[1] = h2r[2*s  ][1] & __vcmpeq2(ax2[2*s  ][1], rr2);
                am[2] = h2r[2*s+1][0] & __vcmpeq2(ax2[2*s+1][0], rr2);
                am[3] = h2r[2*s+1][1] & __vcmpeq2(ax2[2*s+1][1], rr2);
                const int kbase = r*64 + jh*32 + s*16;
                const int vrow = kbase + li + (grp&1)*8;
                #pragma unroll
                for (int p=0;p<2;p++){
                    unsigned vb[4];
                    unsigned a = sm32(Vb + vrow*80 + (p*16 + (grp>>1)*8)*2);
                    ldsm4t(vb, a);
                    mma16816(Od[2*p],   am, vb[0], vb[1]);
                    mma16816(Od[2*p+1], am, vb[2], vb[3]);
                }
            }
        }
    }

    // combine jh halves + normalize + store (half out)
    float* Ost = (float*)buf0;     // [64][34]
    if (jh == 1){
        #pragma unroll
        for (int t8=0;t8<4;t8++){
            *(float2*)&Ost[rowg0*34 + t8*8 + cp2]     = make_float2(Od[t8][0], Od[t8][1]);
            *(float2*)&Ost[(rowg0+8)*34 + t8*8 + cp2] = make_float2(Od[t8][2], Od[t8][3]);
        }
    }
    __syncthreads();
    if (jh == 0){
        const float li0 = 1.f/lrow[rowg0], li1 = 1.f/lrow[rowg0+8];
        #pragma unroll
        for (int t8=0;t8<4;t8++){
            float2 p0 = *(float2*)&Ost[rowg0*34 + t8*8 + cp2];
            float2 p1 = *(float2*)&Ost[(rowg0+8)*34 + t8*8 + cp2];
            __half2 o0 = __floats2half2_rn((Od[t8][0]+p0.x)*li0, (Od[t8][1]+p0.y)*li0);
            __half2 o1 = __floats2half2_rn((Od[t8][2]+p1.x)*li1, (Od[t8][3]+p1.y)*li1);
            *(unsigned*)&O[(size_t)(b*N_+i0+rowg0)*D_   + h*DH_ + t8*8 + cp2] = *(unsigned*)&o0;
            *(unsigned*)&O[(size_t)(b*N_+i0+rowg0+8)*D_ + h*DH_ + t8*8 + cp2] = *(unsigned*)&o1;
        }
    }
}

// =================== launch ===================
extern "C" void kernel_launch(void* const* d_in, const int* in_sizes, int n_in,
                              void* d_out, int out_size)
{
    const float* src = (const float*)d_in[0];
    const int*   adj = (const int*)  d_in[1];
    const float* Wq  = (const float*)d_in[2];  const float* bq  = (const float*)d_in[3];
    const float* Wk  = (const float*)d_in[4];  const float* bk  = (const float*)d_in[5];
    const float* Wv  = (const float*)d_in[6];  const float* bv  = (const float*)d_in[7];
    const float* Wo  = (const float*)d_in[8];  const float* bo  = (const float*)d_in[9];
    const float* W1  = (const float*)d_in[10]; const float* b1  = (const float*)d_in[11];
    const float* W2  = (const float*)d_in[12]; const float* b2  = (const float*)d_in[13];
    const float* g1  = (const float*)d_in[14]; const float* be1 = (const float*)d_in[15];
    const float* g2  = (const float*)d_in[16]; const float* be2 = (const float*)d_in[17];
    float* out = (float*)d_out;

    void* p;
    cudaGetSymbolAddress(&p, g_Qh);   __half* Qh = (__half*)p;
    cudaGetSymbolAddress(&p, g_Kh);   __half* Kh = (__half*)p;
    cudaGetSymbolAddress(&p, g_Vh);   __half* Vh = (__half*)p;
    cudaGetSymbolAddress(&p, g_adjB); unsigned char* adjB = (unsigned char*)p;
    cudaGetSymbolAddress(&p, g_Oh);   __half* Oh = (__half*)p;
    cudaGetSymbolAddress(&p, g_T1);   float* T1 = (float*)p;
    cudaGetSymbolAddress(&p, g_X);    float* Xb = (float*)p;
    cudaGetSymbolAddress(&p, g_Xh);   __half* Xh = (__half*)p;
    cudaGetSymbolAddress(&p, g_F1h);  __half* F1h = (__half*)p;
    cudaGetSymbolAddress(&p, g_T2);   float* T2 = (float*)p;

    const dim3 blk(256);

    // adj -> bytes
    adj2byte<<<(int)((size_t)M_*N_/4/256), blk>>>(adj, adjB);

    // batched Q/K/V projections, half output, Q pre-scaled
    QKVParams qp;
    qp.W[0]=Wq; qp.bias[0]=bq; qp.C[0]=Qh; qp.ldc[0]=D_;   qp.scale[0]=0.17677669529663688f;
    qp.W[1]=Wk; qp.bias[1]=bk; qp.C[1]=Kh; qp.ldc[1]=D_;   qp.scale[1]=1.f;
    for (int r=0;r<R_;r++){
        qp.W[2+r]=Wv + (size_t)r*D_*D_; qp.bias[2+r]=bv + r*D_;
        qp.C[2+r]=Vh + r*D_; qp.ldc[2+r]=R_*D_; qp.scale[2+r]=1.f;
    }
    gemm_qkv<<<dim3(D_/64, M_/128, 6), blk>>>(src, qp);

    // fused relational flash attention -> half O
    cudaFuncSetAttribute(attn_mma, cudaFuncAttributeMaxDynamicSharedMemorySize, ATTN_SMEM);
    attn_mma<<<dim3(N_/64, H_, B_), blk, ATTN_SMEM>>>(Qh, Kh, Vh, adjB, Oh);

    // Wo (half A) -> T1; LN1 -> Xb (float) + Xh (half)
    gemm_h_f<<<dim3(D_/64, M_/128), blk>>>(Oh, Wo, bo, T1, D_, D_, D_);
    ln_fast<true><<<M_/8, blk>>>(src, T1, g1, be1, Xb, Xh);

    // W1 (half A) + GELU -> half F1
    gemm_h_gelu_h<<<dim3(FF_/64, M_/128), blk>>>(Xh, W1, b1, F1h, FF_, D_, FF_);

    // W2 (half A) -> T2; LN2 -> out
    gemm_h_f<<<dim3(D_/64, M_/128), blk>>>(F1h, W2, b2, T2, D_, FF_, D_);
    ln_fast<false><<<M_/8, blk>>>(Xb, T2, g2, be2, out, (__half*)nullptr);
}

// round 16
// speedup vs baseline: 1.4622x; 1.4622x over previous
#include <cuda_runtime.h>
#include <cuda_fp16.h>
#include <mma.h>
#include <math.h>

using namespace nvcuda;

#define B_  8
#define N_  1024
#define D_  256
#define H_  8
#define DH_ 32
#define R_  4
#define FF_ 1024
#define M_  (B_*N_)   // 8192 rows

// ---- scratch (device globals) ----
__device__ __half g_Qh[M_*D_];
__device__ __half g_Kh[M_*D_];
__device__ __half g_Vh[(size_t)M_*R_*D_];     // [n][r*256 + h*32 + d]
__device__ unsigned char g_adjB[(size_t)M_*N_];
__device__ float g_O[M_*D_];
__device__ float g_T1[M_*D_];
__device__ float g_X[M_*D_];
__device__ float g_F1[(size_t)M_*FF_];
__device__ float g_T2[M_*D_];

__device__ __forceinline__ float gelu_f(float x){
    return 0.5f*x*(1.0f + erff(x*0.70710678118654752440f));
}
__device__ __forceinline__ uint2 f4_to_h4(float4 v){
    __half2 lo = __floats2half2_rn(v.x, v.y);
    __half2 hi = __floats2half2_rn(v.z, v.w);
    uint2 r; r.x = *(unsigned*)&lo; r.y = *(unsigned*)&hi; return r;
}

// ---------------- PTX helpers ----------------
__device__ __forceinline__ unsigned sm32(const void* p){
    return (unsigned)__cvta_generic_to_shared(p);
}
__device__ __forceinline__ void cp16(unsigned dst, const void* src){
    asm volatile("cp.async.cg.shared.global [%0], [%1], 16;" :: "r"(dst), "l"(src) : "memory");
}
__device__ __forceinline__ void ldsm4(unsigned* r, unsigned a){
    asm volatile("ldmatrix.sync.aligned.m8n8.x4.shared.b16 {%0,%1,%2,%3}, [%4];"
        : "=r"(r[0]),"=r"(r[1]),"=r"(r[2]),"=r"(r[3]) : "r"(a));
}
__device__ __forceinline__ void ldsm4t(unsigned* r, unsigned a){
    asm volatile("ldmatrix.sync.aligned.m8n8.x4.trans.shared.b16 {%0,%1,%2,%3}, [%4];"
        : "=r"(r[0]),"=r"(r[1]),"=r"(r[2]),"=r"(r[3]) : "r"(a));
}
__device__ __forceinline__ void mma16816(float* c, const unsigned* a, unsigned b0, unsigned b1){
    asm volatile("mma.sync.aligned.m16n8k16.row.col.f32.f16.f16.f32 "
        "{%0,%1,%2,%3}, {%4,%5,%6,%7}, {%8,%9}, {%0,%1,%2,%3};"
        : "+f"(c[0]),"+f"(c[1]),"+f"(c[2]),"+f"(c[3])
        : "r"(a[0]),"r"(a[1]),"r"(a[2]),"r"(a[3]), "r"(b0),"r"(b1));
}

// =================== fp16 wmma GEMM (f32 in, half/float out) ===================
// BM=128, BN=64, BK=32, 256 threads (8 warps 4x2), warp tile 32x32, fp32 accum.
template<bool GELU, bool HOUT>
__device__ __forceinline__ void gemm_body(
    const float* __restrict__ A, const float* __restrict__ Bm,
    const float* __restrict__ bias, void* __restrict__ Cout,
    int Ncols, int K, int ldc, float osc, int bx, int by)
{
    __shared__ float sm[9216];
    __half* As = (__half*)sm;                  // [128][40]
    __half* Bs = (__half*)sm + 5120;           // [32][72]
    float*  Cs = sm;                           // [128][72]

    const int t = threadIdx.x;
    const int w = t >> 5;
    const int wr = w >> 1, wc = w & 1;
    const int row0 = by*128, col0 = bx*64;

    const int rowA = t >> 1, cA = (t & 1)*16;
    const int rowB = t >> 3, cB = (t & 7)*8;

    wmma::fragment<wmma::accumulator,16,16,16,float> acc[2][2];
    #pragma unroll
    for (int i=0;i<2;i++)
        #pragma unroll
        for (int j=0;j<2;j++) wmma::fill_fragment(acc[i][j], 0.f);

    float4 pa[4], pb[2];
    {
        const float* ap = &A[(size_t)(row0+rowA)*K + cA];
        #pragma unroll
        for (int i=0;i<4;i++) pa[i] = *(const float4*)(ap + 4*i);
        const float* bp = &Bm[(size_t)rowB*Ncols + col0 + cB];
        #pragma unroll
        for (int i=0;i<2;i++) pb[i] = *(const float4*)(bp + 4*i);
    }

    for (int k0 = 0; k0 < K; k0 += 32){
        __syncthreads();
        {
            uint4 h0, h1;
            uint2 a0=f4_to_h4(pa[0]), a1=f4_to_h4(pa[1]), a2=f4_to_h4(pa[2]), a3=f4_to_h4(pa[3]);
            h0.x=a0.x; h0.y=a0.y; h0.z=a1.x; h0.w=a1.y;
            h1.x=a2.x; h1.y=a2.y; h1.z=a3.x; h1.w=a3.y;
            *(uint4*)&As[rowA*40 + cA]     = h0;
            *(uint4*)&As[rowA*40 + cA + 8] = h1;
            uint2 b0=f4_to_h4(pb[0]), b1=f4_to_h4(pb[1]);
            uint4 hb; hb.x=b0.x; hb.y=b0.y; hb.z=b1.x; hb.w=b1.y;
            *(uint4*)&Bs[rowB*72 + cB] = hb;
        }
        __syncthreads();

        if (k0 + 32 < K){
            const float* ap = &A[(size_t)(row0+rowA)*K + k0 + 32 + cA];
            #pragma unroll
            for (int i=0;i<4;i++) pa[i] = *(const float4*)(ap + 4*i);
            const float* bp = &Bm[(size_t)(k0+32+rowB)*Ncols + col0 + cB];
            #pragma unroll
            for (int i=0;i<2;i++) pb[i] = *(const float4*)(bp + 4*i);
        }

        #pragma unroll
        for (int kk=0; kk<2; kk++){
            const int k16 = kk*16;
            wmma::fragment<wmma::matrix_a,16,16,16,__half,wmma::row_major> fa[2];
            wmma::fragment<wmma::matrix_b,16,16,16,__half,wmma::row_major> fb[2];
            #pragma unroll
            for (int i=0;i<2;i++)
                wmma::load_matrix_sync(fa[i], &As[(wr*32 + i*16)*40 + k16], 40);
            #pragma unroll
            for (int j=0;j<2;j++)
                wmma::load_matrix_sync(fb[j], &Bs[k16*72 + wc*32 + j*16], 72);
            #pragma unroll
            for (int i=0;i<2;i++)
                #pragma unroll
                for (int j=0;j<2;j++) wmma::mma_sync(acc[i][j], fa[i], fb[j], acc[i][j]);
        }
    }

    __syncthreads();
    #pragma unroll
    for (int i=0;i<2;i++)
        #pragma unroll
        for (int j=0;j<2;j++)
            wmma::store_matrix_sync(&Cs[(wr*32+i*16)*72 + wc*32 + j*16], acc[i][j], 72, wmma::mem_row_major);
    __syncthreads();

    {
        const int row = t >> 1, c0 = (t & 1)*32;
        #pragma unroll
        for (int i=0;i<8;i++){
            float4 v = *(const float4*)&Cs[row*72 + c0 + i*4];
            const int cg = col0 + c0 + i*4;
            v.x += bias[cg+0]; v.y += bias[cg+1]; v.z += bias[cg+2]; v.w += bias[cg+3];
            if (HOUT){ v.x*=osc; v.y*=osc; v.z*=osc; v.w*=osc; }
            if (GELU){ v.x=gelu_f(v.x); v.y=gelu_f(v.y); v.z=gelu_f(v.z); v.w=gelu_f(v.w); }
            if (HOUT){
                __half* Ch = (__half*)Cout;
                uint2 hv = f4_to_h4(v);
                *(uint2*)&Ch[(size_t)(row0+row)*ldc + cg] = hv;
            } else {
                float* Cf = (float*)Cout;
                *(float4*)&Cf[(size_t)(row0+row)*ldc + cg] = v;
            }
        }
    }
}

template<bool GELU>
__global__ void __launch_bounds__(256) gemm_tc(
    const float* __restrict__ A, const float* __restrict__ Bm,
    const float* __restrict__ bias, float* __restrict__ C,
    int Ncols, int K, int ldc)
{
    gemm_body<GELU,false>(A, Bm, bias, C, Ncols, K, ldc, 1.f, blockIdx.x, blockIdx.y);
}

struct QKVParams {
    const float* W[6];
    const float* bias[6];
    __half*      C[6];
    int          ldc[6];
    float        scale[6];
};

__global__ void __launch_bounds__(256) gemm_qkv(
    const float* __restrict__ A, QKVParams p)
{
    const int z = blockIdx.z;
    gemm_body<false,true>(A, p.W[z], p.bias[z], p.C[z], D_, D_, p.ldc[z],
                          p.scale[z], blockIdx.x, blockIdx.y);
}

// adj int32 -> uint8
__global__ void __launch_bounds__(256) adj2byte(
    const int* __restrict__ adj, unsigned char* __restrict__ out)
{
    const size_t i = (size_t)blockIdx.x*256 + threadIdx.x;
    int4 v = ((const int4*)adj)[i];
    uchar4 o;
    o.x=(unsigned char)v.x; o.y=(unsigned char)v.y;
    o.z=(unsigned char)v.z; o.w=(unsigned char)v.w;
    ((uchar4*)out)[i] = o;
}

// =================== fast residual + LayerNorm (warp per row) ===================
__global__ void __launch_bounds__(256) ln_fast(
    const float* __restrict__ X, const float* __restrict__ Y,
    const float* __restrict__ g, const float* __restrict__ beta,
    float* __restrict__ out)
{
    const int w = threadIdx.x >> 5, l = threadIdx.x & 31;
    const size_t row = (size_t)blockIdx.x*8 + w;
    const int col = l*8;
    const float* xp = X + row*D_ + col;
    const float* yp = Y + row*D_ + col;
    float4 x0 = *(const float4*)xp, x1 = *(const float4*)(xp+4);
    float4 y0 = *(const float4*)yp, y1 = *(const float4*)(yp+4);
    float v[8];
    v[0]=x0.x+y0.x; v[1]=x0.y+y0.y; v[2]=x0.z+y0.z; v[3]=x0.w+y0.w;
    v[4]=x1.x+y1.x; v[5]=x1.y+y1.y; v[6]=x1.z+y1.z; v[7]=x1.w+y1.w;

    float s = v[0]+v[1]+v[2]+v[3]+v[4]+v[5]+v[6]+v[7];
    #pragma unroll
    for (int off=16; off>0; off>>=1) s += __shfl_xor_sync(0xffffffffu, s, off);
    const float mean = s * (1.0f/D_);
    float s2 = 0.f;
    #pragma unroll
    for (int i=0;i<8;i++){ const float d = v[i]-mean; s2 += d*d; }
    #pragma unroll
    for (int off=16; off>0; off>>=1) s2 += __shfl_xor_sync(0xffffffffu, s2, off);
    const float rstd = rsqrtf(s2*(1.0f/D_) + 1e-5f);

    float4 g0 = *(const float4*)&g[col],    g1v = *(const float4*)&g[col+4];
    float4 b0 = *(const float4*)&beta[col], b1v = *(const float4*)&beta[col+4];
    float4 o0, o1;
    o0.x=(v[0]-mean)*rstd*g0.x + b0.x;  o0.y=(v[1]-mean)*rstd*g0.y + b0.y;
    o0.z=(v[2]-mean)*rstd*g0.z + b0.z;  o0.w=(v[3]-mean)*rstd*g0.w + b0.w;
    o1.x=(v[4]-mean)*rstd*g1v.x + b1v.x; o1.y=(v[5]-mean)*rstd*g1v.y + b1v.y;
    o1.z=(v[6]-mean)*rstd*g1v.z + b1v.z; o1.w=(v[7]-mean)*rstd*g1v.w + b1v.w;
    float* op = out + row*D_ + col;
    *(float4*)op = o0; *(float4*)(op+4) = o1;
}

// =================== relational flash attention: raw mma + cp.async ===================
#define BUFB 29696
#define ATTN_SMEM 60928

__device__ __forceinline__ void issue_tile(
    unsigned char* bufp, int t, int b, int h, int i0, int j0,
    const __half* __restrict__ Kg, const __half* __restrict__ Vg,
    const unsigned char* __restrict__ adjB)
{
    const int row = t>>2, seg = t&3;
    cp16(sm32(bufp + row*80 + seg*16),
         Kg + (size_t)(b*N_ + j0 + row)*D_ + h*DH_ + seg*8);
    cp16(sm32(bufp + 25600 + row*64 + seg*16),
         adjB + (size_t)(b*N_ + i0 + row)*N_ + j0 + seg*16);
    #pragma unroll
    for (int k2=0;k2<4;k2++){
        const int c = t + 256*k2;
        const int rj = c>>2, sg = c&3;
        const int r = rj>>6, j = rj&63;
        cp16(sm32(bufp + 5120 + rj*80 + sg*16),
             Vg + (size_t)(b*N_ + j0 + j)*(R_*D_) + r*D_ + h*DH_ + sg*8);
    }
}

__global__ void __launch_bounds__(256, 2) attn_mma(
    const __half* __restrict__ Qg, const __half* __restrict__ Kg,
    const __half* __restrict__ Vg, const unsigned char* __restrict__ adjB,
    float* __restrict__ O)
{
    extern __shared__ unsigned char smn[];
    unsigned char* buf0 = smn;
    unsigned char* buf1 = smn + BUFB;
    float* pmax = (float*)(smn + 2*BUFB);          // [2][64]
    float* psum = (float*)(smn + 2*BUFB + 512);    // [2][64]
    float* mrow = (float*)(smn + 2*BUFB + 1024);   // [64]
    float* lrow = (float*)(smn + 2*BUFB + 1280);   // [64]

    const int t = threadIdx.x, l = t & 31, w = t >> 5;
    const int rg = w >> 1, jh = w & 1;
    const int it = blockIdx.x, h = blockIdx.y, b = blockIdx.z;
    const int i0 = it*64;
    const int r0row = l >> 2, cp2 = (l & 3)*2;
    const int rowg0 = rg*16 + r0row;
    const int grp = l >> 3, li = l & 7;

    // stage Q tile into buf1 head
    {
        const int row = t>>2, seg = t&3;
        uint4 qv = *(const uint4*)(Qg + (size_t)(b*N_ + i0 + row)*D_ + h*DH_ + seg*8);
        *(uint4*)(buf1 + row*80 + seg*16) = qv;
    }
    if (t < 64){ mrow[t] = -1e30f; lrow[t] = 0.f; }
    issue_tile(buf0, t, b, h, i0, 0, Kg, Vg, adjB);
    asm volatile("cp.async.commit_group;" ::: "memory");
    __syncthreads();

    // Q fragments (A-operand: m1=row+8, m2=k+8)
    unsigned qf[2][4];
    {
        const int qrow = rg*16 + li + (grp&1)*8;
        #pragma unroll
        for (int kb=0;kb<2;kb++){
            unsigned a = sm32(buf1 + qrow*80 + (kb*16 + ((grp>>1)&1)*8)*2);
            ldsm4(qf[kb], a);
        }
    }

    float Od[4][4];
    #pragma unroll
    for (int i=0;i<4;i++){ Od[i][0]=0;Od[i][1]=0;Od[i][2]=0;Od[i][3]=0; }

    for (int jt = 0; jt < 16; jt++){
        unsigned char* bufc = (jt & 1) ? buf1 : buf0;
        unsigned char* bufn = (jt & 1) ? buf0 : buf1;
        __syncthreads();
        if (jt + 1 < 16){
            issue_tile(bufn, t, b, h, i0, (jt+1)*64, Kg, Vg, adjB);
            asm volatile("cp.async.commit_group;" ::: "memory");
            asm volatile("cp.async.wait_group 1;" ::: "memory");
        } else {
            asm volatile("cp.async.wait_group 0;" ::: "memory");
        }
        __syncthreads();

        // K fragments (B-operand)
        unsigned kf[2][2][4];
        {
            const int krow = jh*32 + li + ((grp>>1)&1)*8;
            #pragma unroll
            for (int kb=0;kb<2;kb++)
                #pragma unroll
                for (int p=0;p<2;p++){
                    unsigned a = sm32(bufc + (krow + p*16)*80 + (kb*16 + (grp&1)*8)*2);
                    ldsm4(kf[kb][p], a);
                }
        }

        // scores
        float sd[4][4];
        #pragma unroll
        for (int t8=0;t8<4;t8++){
            sd[t8][0]=0;sd[t8][1]=0;sd[t8][2]=0;sd[t8][3]=0;
            #pragma unroll
            for (int kb=0;kb<2;kb++){
                const int p = t8>>1, q = (t8&1)*2;
                mma16816(sd[t8], qf[kb], kf[kb][p][q], kf[kb][p][q+1]);
            }
        }

        // online softmax
        float mx0 = -1e30f, mx1 = -1e30f;
        #pragma unroll
        for (int t8=0;t8<4;t8++){
            mx0 = fmaxf(mx0, fmaxf(sd[t8][0], sd[t8][1]));
            mx1 = fmaxf(mx1, fmaxf(sd[t8][2], sd[t8][3]));
        }
        mx0 = fmaxf(mx0, __shfl_xor_sync(0xffffffffu, mx0, 1));
        mx0 = fmaxf(mx0, __shfl_xor_sync(0xffffffffu, mx0, 2));
        mx1 = fmaxf(mx1, __shfl_xor_sync(0xffffffffu, mx1, 1));
        mx1 = fmaxf(mx1, __shfl_xor_sync(0xffffffffu, mx1, 2));
        if ((l&3)==0){
            pmax[jh*64 + rowg0]     = mx0;
            pmax[jh*64 + rowg0 + 8] = mx1;
        }
        __syncthreads();
        const float mold0 = mrow[rowg0], mold1 = mrow[rowg0+8];
        const float mn0 = fmaxf(mold0, fmaxf(pmax[rowg0],   pmax[64+rowg0]));
        const float mn1 = fmaxf(mold1, fmaxf(pmax[rowg0+8], pmax[64+rowg0+8]));
        const float c0 = __expf(mold0 - mn0), c1 = __expf(mold1 - mn1);
        float s0 = 0.f, s1 = 0.f;
        #pragma unroll
        for (int t8=0;t8<4;t8++){
            sd[t8][0] = __expf(sd[t8][0] - mn0);
            sd[t8][1] = __expf(sd[t8][1] - mn0);
            sd[t8][2] = __expf(sd[t8][2] - mn1);
            sd[t8][3] = __expf(sd[t8][3] - mn1);
            s0 += sd[t8][0] + sd[t8][1];
            s1 += sd[t8][2] + sd[t8][3];
        }
        s0 += __shfl_xor_sync(0xffffffffu, s0, 1);
        s0 += __shfl_xor_sync(0xffffffffu, s0, 2);
        s1 += __shfl_xor_sync(0xffffffffu, s1, 1);
        s1 += __shfl_xor_sync(0xffffffffu, s1, 2);
        if ((l&3)==0){
            psum[jh*64 + rowg0]     = s0;
            psum[jh*64 + rowg0 + 8] = s1;
        }
        __syncthreads();
        if (jh==0 && (l&3)==0){
            lrow[rowg0]   = lrow[rowg0]  *c0 + psum[rowg0]   + psum[64+rowg0];
            lrow[rowg0+8] = lrow[rowg0+8]*c1 + psum[rowg0+8] + psum[64+rowg0+8];
            mrow[rowg0]   = mn0;
            mrow[rowg0+8] = mn1;
        }

        #pragma unroll
        for (int t8=0;t8<4;t8++){
            Od[t8][0]*=c0; Od[t8][1]*=c0; Od[t8][2]*=c1; Od[t8][3]*=c1;
        }

        // p -> half2 + adj codes
        unsigned h2r[4][2], ax2[4][2];
        const unsigned char* adjT = bufc + 25600;
        #pragma unroll
        for (int t8=0;t8<4;t8++){
            __half2 p01 = __floats2half2_rn(sd[t8][0], sd[t8][1]);
            __half2 p23 = __floats2half2_rn(sd[t8][2], sd[t8][3]);
            h2r[t8][0] = *(unsigned*)&p01;
            h2r[t8][1] = *(unsigned*)&p23;
            const int colo = jh*32 + t8*8 + cp2;
            unsigned a0 = *(const unsigned short*)(adjT + rowg0*64 + colo);
            unsigned a1 = *(const unsigned short*)(adjT + (rowg0+8)*64 + colo);
            ax2[t8][0] = (a0 & 0xffu) | ((a0 & 0xff00u) << 8);
            ax2[t8][1] = (a1 & 0xffu) | ((a1 & 0xff00u) << 8);
        }

        // PV: Od += sum_r (P .* (adj==r)) @ V_r
        const unsigned char* Vb = bufc + 5120;
        #pragma unroll
        for (int r=0;r<R_;r++){
            const unsigned rr2 = (unsigned)r * 0x00010001u;
            #pragma unroll
            for (int s=0;s<2;s++){
                unsigned am[4];
                am[0] = h2r[2*s  ][0] & __vcmpeq2(ax2[2*s  ][0], rr2);
                am[1] = h2r[2*s  ][1] & __vcmpeq2(ax2[2*s  ][1], rr2);
                am[2] = h2r[2*s+1][0] & __vcmpeq2(ax2[2*s+1][0], rr2);
                am[3] = h2r[2*s+1][1] & __vcmpeq2(ax2[2*s+1][1], rr2);
                const int kbase = r*64 + jh*32 + s*16;
                const int vrow = kbase + li + (grp&1)*8;
                #pragma unroll
                for (int p=0;p<2;p++){
                    unsigned vb[4];
                    unsigned a = sm32(Vb + vrow*80 + (p*16 + (grp>>1)*8)*2);
                    ldsm4t(vb, a);
                    mma16816(Od[2*p],   am, vb[0], vb[1]);
                    mma16816(Od[2*p+1], am, vb[2], vb[3]);
                }
            }
        }
    }

    // combine jh halves + normalize + store
    float* Ost = (float*)buf0;     // [64][34]
    if (jh == 1){
        #pragma unroll
        for (int t8=0;t8<4;t8++){
            *(float2*)&Ost[rowg0*34 + t8*8 + cp2]     = make_float2(Od[t8][0], Od[t8][1]);
            *(float2*)&Ost[(rowg0+8)*34 + t8*8 + cp2] = make_float2(Od[t8][2], Od[t8][3]);
        }
    }
    __syncthreads();
    if (jh == 0){
        const float li0 = 1.f/lrow[rowg0], li1 = 1.f/lrow[rowg0+8];
        #pragma unroll
        for (int t8=0;t8<4;t8++){
            float2 p0 = *(float2*)&Ost[rowg0*34 + t8*8 + cp2];
            float2 p1 = *(float2*)&Ost[(rowg0+8)*34 + t8*8 + cp2];
            float2 o0 = make_float2((Od[t8][0]+p0.x)*li0, (Od[t8][1]+p0.y)*li0);
            float2 o1 = make_float2((Od[t8][2]+p1.x)*li1, (Od[t8][3]+p1.y)*li1);
            *(float2*)&O[(size_t)(b*N_+i0+rowg0)*D_   + h*DH_ + t8*8 + cp2] = o0;
            *(float2*)&O[(size_t)(b*N_+i0+rowg0+8)*D_ + h*DH_ + t8*8 + cp2] = o1;
        }
    }
}

// =================== launch ===================
extern "C" void kernel_launch(void* const* d_in, const int* in_sizes, int n_in,
                              void* d_out, int out_size)
{
    const float* src = (const float*)d_in[0];
    const int*   adj = (const int*)  d_in[1];
    const float* Wq  = (const float*)d_in[2];  const float* bq  = (const float*)d_in[3];
    const float* Wk  = (const float*)d_in[4];  const float* bk  = (const float*)d_in[5];
    const float* Wv  = (const float*)d_in[6];  const float* bv  = (const float*)d_in[7];
    const float* Wo  = (const float*)d_in[8];  const float* bo  = (const float*)d_in[9];
    const float* W1  = (const float*)d_in[10]; const float* b1  = (const float*)d_in[11];
    const float* W2  = (const float*)d_in[12]; const float* b2  = (const float*)d_in[13];
    const float* g1  = (const float*)d_in[14]; const float* be1 = (const float*)d_in[15];
    const float* g2  = (const float*)d_in[16]; const float* be2 = (const float*)d_in[17];
    float* out = (float*)d_out;

    void* p;
    cudaGetSymbolAddress(&p, g_Qh);   __half* Qh = (__half*)p;
    cudaGetSymbolAddress(&p, g_Kh);   __half* Kh = (__half*)p;
    cudaGetSymbolAddress(&p, g_Vh);   __half* Vh = (__half*)p;
    cudaGetSymbolAddress(&p, g_adjB); unsigned char* adjB = (unsigned char*)p;
    cudaGetSymbolAddress(&p, g_O);    float* Ob = (float*)p;
    cudaGetSymbolAddress(&p, g_T1);   float* T1 = (float*)p;
    cudaGetSymbolAddress(&p, g_X);    float* Xb = (float*)p;
    cudaGetSymbolAddress(&p, g_F1);   float* F1 = (float*)p;
    cudaGetSymbolAddress(&p, g_T2);   float* T2 = (float*)p;

    const dim3 blk(256);

    // adj -> bytes
    adj2byte<<<(int)((size_t)M_*N_/4/256), blk>>>(adj, adjB);

    // batched Q/K/V projections, half output, Q pre-scaled
    QKVParams qp;
    qp.W[0]=Wq; qp.bias[0]=bq; qp.C[0]=Qh; qp.ldc[0]=D_;   qp.scale[0]=0.17677669529663688f;
    qp.W[1]=Wk; qp.bias[1]=bk; qp.C[1]=Kh; qp.ldc[1]=D_;   qp.scale[1]=1.f;
    for (int r=0;r<R_;r++){
        qp.W[2+r]=Wv + (size_t)r*D_*D_; qp.bias[2+r]=bv + r*D_;
        qp.C[2+r]=Vh + r*D_; qp.ldc[2+r]=R_*D_; qp.scale[2+r]=1.f;
    }
    gemm_qkv<<<dim3(D_/64, M_/128, 6), blk>>>(src, qp);

    // fused relational flash attention -> float O
    cudaFuncSetAttribute(attn_mma, cudaFuncAttributeMaxDynamicSharedMemorySize, ATTN_SMEM);
    attn_mma<<<dim3(N_/64, H_, B_), blk, ATTN_SMEM>>>(Qh, Kh, Vh, adjB, Ob);

    // output projection + LN1
    gemm_tc<false><<<dim3(D_/64, M_/128), blk>>>(Ob, Wo, bo, T1, D_, D_, D_);
    ln_fast<<<M_/8, blk>>>(src, T1, g1, be1, Xb);

    // FFN + LN2
    gemm_tc<true ><<<dim3(FF_/64, M_/128), blk>>>(Xb, W1, b1, F1, FF_, D_, FF_);
    gemm_tc<false><<<dim3(D_/64, M_/128), blk>>>(F1, W2, b2, T2, D_, FF_, D_);
    ln_fast<<<M_/8, blk>>>(Xb, T2, g2, be2, out);
}

// round 17
// speedup vs baseline: 1.5294x; 1.0459x over previous
#include <cuda_runtime.h>
#include <cuda_fp16.h>
#include <mma.h>
#include <math.h>

using namespace nvcuda;

#define B_  8
#define N_  1024
#define D_  256
#define H_  8
#define DH_ 32
#define R_  4
#define FF_ 1024
#define M_  (B_*N_)   // 8192 rows

// ---- scratch (device globals) ----
__device__ __half g_Qh[M_*D_];
__device__ __half g_Kh[M_*D_];
__device__ __half g_Vh[(size_t)M_*R_*D_];     // [n][r*256 + h*32 + d]
__device__ unsigned char g_adjB[(size_t)M_*N_];
__device__ float g_O[M_*D_];
__device__ float g_T1[M_*D_];
__device__ float g_X[M_*D_];
__device__ float g_F1[(size_t)M_*FF_];
__device__ float g_T2[M_*D_];

__device__ __forceinline__ float gelu_f(float x){
    return 0.5f*x*(1.0f + erff(x*0.70710678118654752440f));
}
__device__ __forceinline__ uint2 f4_to_h4(float4 v){
    __half2 lo = __floats2half2_rn(v.x, v.y);
    __half2 hi = __floats2half2_rn(v.z, v.w);
    uint2 r; r.x = *(unsigned*)&lo; r.y = *(unsigned*)&hi; return r;
}

// ---------------- PTX helpers ----------------
__device__ __forceinline__ unsigned sm32(const void* p){
    return (unsigned)__cvta_generic_to_shared(p);
}
__device__ __forceinline__ void cp16(unsigned dst, const void* src){
    asm volatile("cp.async.cg.shared.global [%0], [%1], 16;" :: "r"(dst), "l"(src) : "memory");
}
__device__ __forceinline__ void ldsm4(unsigned* r, unsigned a){
    asm volatile("ldmatrix.sync.aligned.m8n8.x4.shared.b16 {%0,%1,%2,%3}, [%4];"
        : "=r"(r[0]),"=r"(r[1]),"=r"(r[2]),"=r"(r[3]) : "r"(a));
}
__device__ __forceinline__ void ldsm4t(unsigned* r, unsigned a){
    asm volatile("ldmatrix.sync.aligned.m8n8.x4.trans.shared.b16 {%0,%1,%2,%3}, [%4];"
        : "=r"(r[0]),"=r"(r[1]),"=r"(r[2]),"=r"(r[3]) : "r"(a));
}
__device__ __forceinline__ void mma16816(float* c, const unsigned* a, unsigned b0, unsigned b1){
    asm volatile("mma.sync.aligned.m16n8k16.row.col.f32.f16.f16.f32 "
        "{%0,%1,%2,%3}, {%4,%5,%6,%7}, {%8,%9}, {%0,%1,%2,%3};"
        : "+f"(c[0]),"+f"(c[1]),"+f"(c[2]),"+f"(c[3])
        : "r"(a[0]),"r"(a[1]),"r"(a[2]),"r"(a[3]), "r"(b0),"r"(b1));
}

// =================== fp16 wmma GEMM (f32 in, half/float out) ===================
// BM=128, BN=64, BK=32, 256 threads (8 warps 4x2), warp tile 32x32, fp32 accum.
template<bool GELU, bool HOUT>
__device__ __forceinline__ void gemm_body(
    const float* __restrict__ A, const float* __restrict__ Bm,
    const float* __restrict__ bias, void* __restrict__ Cout,
    int Ncols, int K, int ldc, float osc, int bx, int by)
{
    __shared__ float sm[9216];
    __half* As = (__half*)sm;                  // [128][40]
    __half* Bs = (__half*)sm + 5120;           // [32][72]
    float*  Cs = sm;                           // [128][72]

    const int t = threadIdx.x;
    const int w = t >> 5;
    const int wr = w >> 1, wc = w & 1;
    const int row0 = by*128, col0 = bx*64;

    const int rowA = t >> 1, cA = (t & 1)*16;
    const int rowB = t >> 3, cB = (t & 7)*8;

    wmma::fragment<wmma::accumulator,16,16,16,float> acc[2][2];
    #pragma unroll
    for (int i=0;i<2;i++)
        #pragma unroll
        for (int j=0;j<2;j++) wmma::fill_fragment(acc[i][j], 0.f);

    float4 pa[4], pb[2];
    {
        const float* ap = &A[(size_t)(row0+rowA)*K + cA];
        #pragma unroll
        for (int i=0;i<4;i++) pa[i] = *(const float4*)(ap + 4*i);
        const float* bp = &Bm[(size_t)rowB*Ncols + col0 + cB];
        #pragma unroll
        for (int i=0;i<2;i++) pb[i] = *(const float4*)(bp + 4*i);
    }

    for (int k0 = 0; k0 < K; k0 += 32){
        __syncthreads();
        {
            uint4 h0, h1;
            uint2 a0=f4_to_h4(pa[0]), a1=f4_to_h4(pa[1]), a2=f4_to_h4(pa[2]), a3=f4_to_h4(pa[3]);
            h0.x=a0.x; h0.y=a0.y; h0.z=a1.x; h0.w=a1.y;
            h1.x=a2.x; h1.y=a2.y; h1.z=a3.x; h1.w=a3.y;
            *(uint4*)&As[rowA*40 + cA]     = h0;
            *(uint4*)&As[rowA*40 + cA + 8] = h1;
            uint2 b0=f4_to_h4(pb[0]), b1=f4_to_h4(pb[1]);
            uint4 hb; hb.x=b0.x; hb.y=b0.y; hb.z=b1.x; hb.w=b1.y;
            *(uint4*)&Bs[rowB*72 + cB] = hb;
        }
        __syncthreads();

        if (k0 + 32 < K){
            const float* ap = &A[(size_t)(row0+rowA)*K + k0 + 32 + cA];
            #pragma unroll
            for (int i=0;i<4;i++) pa[i] = *(const float4*)(ap + 4*i);
            const float* bp = &Bm[(size_t)(k0+32+rowB)*Ncols + col0 + cB];
            #pragma unroll
            for (int i=0;i<2;i++) pb[i] = *(const float4*)(bp + 4*i);
        }

        #pragma unroll
        for (int kk=0; kk<2; kk++){
            const int k16 = kk*16;
            wmma::fragment<wmma::matrix_a,16,16,16,__half,wmma::row_major> fa[2];
            wmma::fragment<wmma::matrix_b,16,16,16,__half,wmma::row_major> fb[2];
            #pragma unroll
            for (int i=0;i<2;i++)
                wmma::load_matrix_sync(fa[i], &As[(wr*32 + i*16)*40 + k16], 40);
            #pragma unroll
            for (int j=0;j<2;j++)
                wmma::load_matrix_sync(fb[j], &Bs[k16*72 + wc*32 + j*16], 72);
            #pragma unroll
            for (int i=0;i<2;i++)
                #pragma unroll
                for (int j=0;j<2;j++) wmma::mma_sync(acc[i][j], fa[i], fb[j], acc[i][j]);
        }
    }

    __syncthreads();
    #pragma unroll
    for (int i=0;i<2;i++)
        #pragma unroll
        for (int j=0;j<2;j++)
            wmma::store_matrix_sync(&Cs[(wr*32+i*16)*72 + wc*32 + j*16], acc[i][j], 72, wmma::mem_row_major);
    __syncthreads();

    {
        const int row = t >> 1, c0 = (t & 1)*32;
        #pragma unroll
        for (int i=0;i<8;i++){
            float4 v = *(const float4*)&Cs[row*72 + c0 + i*4];
            const int cg = col0 + c0 + i*4;
            v.x += bias[cg+0]; v.y += bias[cg+1]; v.z += bias[cg+2]; v.w += bias[cg+3];
            if (HOUT){ v.x*=osc; v.y*=osc; v.z*=osc; v.w*=osc; }
            if (GELU){ v.x=gelu_f(v.x); v.y=gelu_f(v.y); v.z=gelu_f(v.z); v.w=gelu_f(v.w); }
            if (HOUT){
                __half* Ch = (__half*)Cout;
                uint2 hv = f4_to_h4(v);
                *(uint2*)&Ch[(size_t)(row0+row)*ldc + cg] = hv;
            } else {
                float* Cf = (float*)Cout;
                *(float4*)&Cf[(size_t)(row0+row)*ldc + cg] = v;
            }
        }
    }
}

template<bool GELU>
__global__ void __launch_bounds__(256) gemm_tc(
    const float* __restrict__ A, const float* __restrict__ Bm,
    const float* __restrict__ bias, float* __restrict__ C,
    int Ncols, int K, int ldc)
{
    gemm_body<GELU,false>(A, Bm, bias, C, Ncols, K, ldc, 1.f, blockIdx.x, blockIdx.y);
}

struct QKVParams {
    const float* W[6];
    const float* bias[6];
    __half*      C[6];
    int          ldc[6];
    float        scale[6];
};

__global__ void __launch_bounds__(256) gemm_qkv(
    const float* __restrict__ A, QKVParams p)
{
    const int z = blockIdx.z;
    gemm_body<false,true>(A, p.W[z], p.bias[z], p.C[z], D_, D_, p.ldc[z],
                          p.scale[z], blockIdx.x, blockIdx.y);
}

// adj int32 -> uint8
__global__ void __launch_bounds__(256) adj2byte(
    const int* __restrict__ adj, unsigned char* __restrict__ out)
{
    const size_t i = (size_t)blockIdx.x*256 + threadIdx.x;
    int4 v = ((const int4*)adj)[i];
    uchar4 o;
    o.x=(unsigned char)v.x; o.y=(unsigned char)v.y;
    o.z=(unsigned char)v.z; o.w=(unsigned char)v.w;
    ((uchar4*)out)[i] = o;
}

// =================== fast residual + LayerNorm (warp per row) ===================
__global__ void __launch_bounds__(256) ln_fast(
    const float* __restrict__ X, const float* __restrict__ Y,
    const float* __restrict__ g, const float* __restrict__ beta,
    float* __restrict__ out)
{
    const int w = threadIdx.x >> 5, l = threadIdx.x & 31;
    const size_t row = (size_t)blockIdx.x*8 + w;
    const int col = l*8;
    const float* xp = X + row*D_ + col;
    const float* yp = Y + row*D_ + col;
    float4 x0 = *(const float4*)xp, x1 = *(const float4*)(xp+4);
    float4 y0 = *(const float4*)yp, y1 = *(const float4*)(yp+4);
    float v[8];
    v[0]=x0.x+y0.x; v[1]=x0.y+y0.y; v[2]=x0.z+y0.z; v[3]=x0.w+y0.w;
    v[4]=x1.x+y1.x; v[5]=x1.y+y1.y; v[6]=x1.z+y1.z; v[7]=x1.w+y1.w;

    float s = v[0]+v[1]+v[2]+v[3]+v[4]+v[5]+v[6]+v[7];
    #pragma unroll
    for (int off=16; off>0; off>>=1) s += __shfl_xor_sync(0xffffffffu, s, off);
    const float mean = s * (1.0f/D_);
    float s2 = 0.f;
    #pragma unroll
    for (int i=0;i<8;i++){ const float d = v[i]-mean; s2 += d*d; }
    #pragma unroll
    for (int off=16; off>0; off>>=1) s2 += __shfl_xor_sync(0xffffffffu, s2, off);
    const float rstd = rsqrtf(s2*(1.0f/D_) + 1e-5f);

    float4 g0 = *(const float4*)&g[col],    g1v = *(const float4*)&g[col+4];
    float4 b0 = *(const float4*)&beta[col], b1v = *(const float4*)&beta[col+4];
    float4 o0, o1;
    o0.x=(v[0]-mean)*rstd*g0.x + b0.x;  o0.y=(v[1]-mean)*rstd*g0.y + b0.y;
    o0.z=(v[2]-mean)*rstd*g0.z + b0.z;  o0.w=(v[3]-mean)*rstd*g0.w + b0.w;
    o1.x=(v[4]-mean)*rstd*g1v.x + b1v.x; o1.y=(v[5]-mean)*rstd*g1v.y + b1v.y;
    o1.z=(v[6]-mean)*rstd*g1v.z + b1v.z; o1.w=(v[7]-mean)*rstd*g1v.w + b1v.w;
    float* op = out + row*D_ + col;
    *(float4*)op = o0; *(float4*)(op+4) = o1;
}

// =================== relational flash attention: 128-query tiles, register softmax ===================
// grid (N/128, H, B) = 512 CTAs, 256 thr (8 warps, warp w owns rows w*16..w*16+15).
// Buffer: K[64][80] | V[256][80] | adj[128][64]  = 33792 B; double buffered = 67584 B.
#define BUFB 33792
#define ATTN_SMEM (2*BUFB)

__device__ __forceinline__ void issue_tile(
    unsigned char* bufp, int t, int b, int h, int i0, int j0,
    const __half* __restrict__ Kg, const __half* __restrict__ Vg,
    const unsigned char* __restrict__ adjB)
{
    // K tile: 64 rows x 64B (stride 80)
    {
        const int row = t>>2, seg = t&3;
        cp16(sm32(bufp + row*80 + seg*16),
             Kg + (size_t)(b*N_ + j0 + row)*D_ + h*DH_ + seg*8);
    }
    // V tiles: 256 rows (r*64+j) x 64B
    #pragma unroll
    for (int k2=0;k2<4;k2++){
        const int c = t + 256*k2;
        const int rj = c>>2, sg = c&3;
        const int r = rj>>6, j = rj&63;
        cp16(sm32(bufp + 5120 + rj*80 + sg*16),
             Vg + (size_t)(b*N_ + j0 + j)*(R_*D_) + r*D_ + h*DH_ + sg*8);
    }
    // adj tile: 128 query rows x 64B
    #pragma unroll
    for (int k2=0;k2<2;k2++){
        const int c = t + 256*k2;
        const int row = c>>2, seg = c&3;
        cp16(sm32(bufp + 25600 + row*64 + seg*16),
             adjB + (size_t)(b*N_ + i0 + row)*N_ + j0 + seg*16);
    }
}

__global__ void __launch_bounds__(256, 2) attn_mma(
    const __half* __restrict__ Qg, const __half* __restrict__ Kg,
    const __half* __restrict__ Vg, const unsigned char* __restrict__ adjB,
    float* __restrict__ O)
{
    extern __shared__ unsigned char smn[];
    unsigned char* buf0 = smn;
    unsigned char* buf1 = smn + BUFB;

    const int t = threadIdx.x, l = t & 31, w = t >> 5;
    const int it = blockIdx.x, h = blockIdx.y, b = blockIdx.z;
    const int i0 = it*128;
    const int r0row = l >> 2, cp2 = (l & 3)*2;
    const int rowg0 = w*16 + r0row;
    const int grp = l >> 3, li = l & 7;

    // stage Q tile (128 rows x 64B, stride 80) into buf1
    {
        const int row = t>>1, seg = t&1;
        const __half* qp = Qg + (size_t)(b*N_ + i0 + row)*D_ + h*DH_ + seg*16;
        uint4 q0 = *(const uint4*)qp;
        uint4 q1 = *(const uint4*)(qp+8);
        *(uint4*)(buf1 + row*80 + seg*32)      = q0;
        *(uint4*)(buf1 + row*80 + seg*32 + 16) = q1;
    }
    issue_tile(buf0, t, b, h, i0, 0, Kg, Vg, adjB);
    asm volatile("cp.async.commit_group;" ::: "memory");
    __syncthreads();

    // Q fragments (A-operand: m1=row+8, m2=k+8)
    unsigned qf[2][4];
    {
        const int qrow = w*16 + li + (grp&1)*8;
        #pragma unroll
        for (int kb=0;kb<2;kb++){
            unsigned a = sm32(buf1 + qrow*80 + (kb*16 + ((grp>>1)&1)*8)*2);
            ldsm4(qf[kb], a);
        }
    }

    float Od[4][4];
    #pragma unroll
    for (int i=0;i<4;i++){ Od[i][0]=0;Od[i][1]=0;Od[i][2]=0;Od[i][3]=0; }
    float m0 = -1e30f, m1 = -1e30f, l0 = 0.f, l1 = 0.f;

    for (int jt = 0; jt < 16; jt++){
        unsigned char* bufc = (jt & 1) ? buf1 : buf0;
        unsigned char* bufn = (jt & 1) ? buf0 : buf1;
        __syncthreads();
        if (jt + 1 < 16){
            issue_tile(bufn, t, b, h, i0, (jt+1)*64, Kg, Vg, adjB);
            asm volatile("cp.async.commit_group;" ::: "memory");
            asm volatile("cp.async.wait_group 1;" ::: "memory");
        } else {
            asm volatile("cp.async.wait_group 0;" ::: "memory");
        }
        __syncthreads();

        // ---- scores: 16 rows x 64 keys per warp, sd[8] n8-tiles ----
        float sd[8][4];
        #pragma unroll
        for (int ng=0; ng<4; ng++){
            unsigned kf[2][4];
            const int krow = ng*16 + li + ((grp>>1)&1)*8;
            #pragma unroll
            for (int kb=0;kb<2;kb++){
                unsigned a = sm32(bufc + krow*80 + (kb*16 + (grp&1)*8)*2);
                ldsm4(kf[kb], a);
            }
            #pragma unroll
            for (int u=0;u<2;u++){
                const int t8 = ng*2 + u;
                sd[t8][0]=0;sd[t8][1]=0;sd[t8][2]=0;sd[t8][3]=0;
                #pragma unroll
                for (int kb=0;kb<2;kb++)
                    mma16816(sd[t8], qf[kb], kf[kb][u*2], kf[kb][u*2+1]);
            }
        }

        // ---- fully register-resident online softmax (quad shuffles) ----
        float mx0 = -1e30f, mx1 = -1e30f;
        #pragma unroll
        for (int t8=0;t8<8;t8++){
            mx0 = fmaxf(mx0, fmaxf(sd[t8][0], sd[t8][1]));
            mx1 = fmaxf(mx1, fmaxf(sd[t8][2], sd[t8][3]));
        }
        mx0 = fmaxf(mx0, __shfl_xor_sync(0xffffffffu, mx0, 1));
        mx0 = fmaxf(mx0, __shfl_xor_sync(0xffffffffu, mx0, 2));
        mx1 = fmaxf(mx1, __shfl_xor_sync(0xffffffffu, mx1, 1));
        mx1 = fmaxf(mx1, __shfl_xor_sync(0xffffffffu, mx1, 2));
        const float mn0 = fmaxf(m0, mx0), mn1 = fmaxf(m1, mx1);
        const float c0 = __expf(m0 - mn0), c1 = __expf(m1 - mn1);
        m0 = mn0; m1 = mn1;
        float s0 = 0.f, s1 = 0.f;
        #pragma unroll
        for (int t8=0;t8<8;t8++){
            sd[t8][0] = __expf(sd[t8][0] - mn0);
            sd[t8][1] = __expf(sd[t8][1] - mn0);
            sd[t8][2] = __expf(sd[t8][2] - mn1);
            sd[t8][3] = __expf(sd[t8][3] - mn1);
            s0 += sd[t8][0] + sd[t8][1];
            s1 += sd[t8][2] + sd[t8][3];
        }
        s0 += __shfl_xor_sync(0xffffffffu, s0, 1);
        s0 += __shfl_xor_sync(0xffffffffu, s0, 2);
        s1 += __shfl_xor_sync(0xffffffffu, s1, 1);
        s1 += __shfl_xor_sync(0xffffffffu, s1, 2);
        l0 = l0*c0 + s0;
        l1 = l1*c1 + s1;

        #pragma unroll
        for (int t8=0;t8<4;t8++){
            Od[t8][0]*=c0; Od[t8][1]*=c0; Od[t8][2]*=c1; Od[t8][3]*=c1;
        }

        // p -> half2 + adj codes
        unsigned h2r[8][2], ax2[8][2];
        const unsigned char* adjT = bufc + 25600;
        #pragma unroll
        for (int t8=0;t8<8;t8++){
            __half2 p01 = __floats2half2_rn(sd[t8][0], sd[t8][1]);
            __half2 p23 = __floats2half2_rn(sd[t8][2], sd[t8][3]);
            h2r[t8][0] = *(unsigned*)&p01;
            h2r[t8][1] = *(unsigned*)&p23;
            const int colo = t8*8 + cp2;
            unsigned a0 = *(const unsigned short*)(adjT + rowg0*64 + colo);
            unsigned a1 = *(const unsigned short*)(adjT + (rowg0+8)*64 + colo);
            ax2[t8][0] = (a0 & 0xffu) | ((a0 & 0xff00u) << 8);
            ax2[t8][1] = (a1 & 0xffu) | ((a1 & 0xff00u) << 8);
        }

        // ---- PV: Od += sum_r (P .* (adj==r)) @ V_r ----
        const unsigned char* Vb = bufc + 5120;
        #pragma unroll
        for (int r=0;r<R_;r++){
            const unsigned rr2 = (unsigned)r * 0x00010001u;
            #pragma unroll
            for (int s=0;s<4;s++){
                unsigned am[4];
                am[0] = h2r[2*s  ][0] & __vcmpeq2(ax2[2*s  ][0], rr2);
                am[1] = h2r[2*s  ][1] & __vcmpeq2(ax2[2*s  ][1], rr2);
                am[2] = h2r[2*s+1][0] & __vcmpeq2(ax2[2*s+1][0], rr2);
                am[3] = h2r[2*s+1][1] & __vcmpeq2(ax2[2*s+1][1], rr2);
                const int vrow = r*64 + s*16 + li + (grp&1)*8;
                #pragma unroll
                for (int p=0;p<2;p++){
                    unsigned vb[4];
                    unsigned a = sm32(Vb + vrow*80 + (p*16 + (grp>>1)*8)*2);
                    ldsm4t(vb, a);
                    mma16816(Od[2*p],   am, vb[0], vb[1]);
                    mma16816(Od[2*p+1], am, vb[2], vb[3]);
                }
            }
        }
    }

    // ---- normalize + store (rows owned entirely by this warp) ----
    {
        const float li0 = 1.f/l0, li1 = 1.f/l1;
        #pragma unroll
        for (int t8=0;t8<4;t8++){
            float2 o0 = make_float2(Od[t8][0]*li0, Od[t8][1]*li0);
            float2 o1 = make_float2(Od[t8][2]*li1, Od[t8][3]*li1);
            *(float2*)&O[(size_t)(b*N_+i0+rowg0)*D_   + h*DH_ + t8*8 + cp2] = o0;
            *(float2*)&O[(size_t)(b*N_+i0+rowg0+8)*D_ + h*DH_ + t8*8 + cp2] = o1;
        }
    }
}

// =================== launch ===================
extern "C" void kernel_launch(void* const* d_in, const int* in_sizes, int n_in,
                              void* d_out, int out_size)
{
    const float* src = (const float*)d_in[0];
    const int*   adj = (const int*)  d_in[1];
    const float* Wq  = (const float*)d_in[2];  const float* bq  = (const float*)d_in[3];
    const float* Wk  = (const float*)d_in[4];  const float* bk  = (const float*)d_in[5];
    const float* Wv  = (const float*)d_in[6];  const float* bv  = (const float*)d_in[7];
    const float* Wo  = (const float*)d_in[8];  const float* bo  = (const float*)d_in[9];
    const float* W1  = (const float*)d_in[10]; const float* b1  = (const float*)d_in[11];
    const float* W2  = (const float*)d_in[12]; const float* b2  = (const float*)d_in[13];
    const float* g1  = (const float*)d_in[14]; const float* be1 = (const float*)d_in[15];
    const float* g2  = (const float*)d_in[16]; const float* be2 = (const float*)d_in[17];
    float* out = (float*)d_out;

    void* p;
    cudaGetSymbolAddress(&p, g_Qh);   __half* Qh = (__half*)p;
    cudaGetSymbolAddress(&p, g_Kh);   __half* Kh = (__half*)p;
    cudaGetSymbolAddress(&p, g_Vh);   __half* Vh = (__half*)p;
    cudaGetSymbolAddress(&p, g_adjB); unsigned char* adjB = (unsigned char*)p;
    cudaGetSymbolAddress(&p, g_O);    float* Ob = (float*)p;
    cudaGetSymbolAddress(&p, g_T1);   float* T1 = (float*)p;
    cudaGetSymbolAddress(&p, g_X);    float* Xb = (float*)p;
    cudaGetSymbolAddress(&p, g_F1);   float* F1 = (float*)p;
    cudaGetSymbolAddress(&p, g_T2);   float* T2 = (float*)p;

    const dim3 blk(256);

    // adj -> bytes
    adj2byte<<<(int)((size_t)M_*N_/4/256), blk>>>(adj, adjB);

    // batched Q/K/V projections, half output, Q pre-scaled
    QKVParams qp;
    qp.W[0]=Wq; qp.bias[0]=bq; qp.C[0]=Qh; qp.ldc[0]=D_;   qp.scale[0]=0.17677669529663688f;
    qp.W[1]=Wk; qp.bias[1]=bk; qp.C[1]=Kh; qp.ldc[1]=D_;   qp.scale[1]=1.f;
    for (int r=0;r<R_;r++){
        qp.W[2+r]=Wv + (size_t)r*D_*D_; qp.bias[2+r]=bv + r*D_;
        qp.C[2+r]=Vh + r*D_; qp.ldc[2+r]=R_*D_; qp.scale[2+r]=1.f;
    }
    gemm_qkv<<<dim3(D_/64, M_/128, 6), blk>>>(src, qp);

    // fused relational flash attention -> float O
    cudaFuncSetAttribute(attn_mma, cudaFuncAttributeMaxDynamicSharedMemorySize, ATTN_SMEM);
    attn_mma<<<dim3(N_/128, H_, B_), blk, ATTN_SMEM>>>(Qh, Kh, Vh, adjB, Ob);

    // output projection + LN1
    gemm_tc<false><<<dim3(D_/64, M_/128), blk>>>(Ob, Wo, bo, T1, D_, D_, D_);
    ln_fast<<<M_/8, blk>>>(src, T1, g1, be1, Xb);

    // FFN + LN2
    gemm_tc<true ><<<dim3(FF_/64, M_/128), blk>>>(Xb, W1, b1, F1, FF_, D_, FF_);
    gemm_tc<false><<<dim3(D_/64, M_/128), blk>>>(F1, W2, b2, T2, D_, FF_, D_);
    ln_fast<<<M_/8, blk>>>(Xb, T2, g2, be2, out);
}